// round 14
// baseline (speedup 1.0000x reference)
#include <cuda_runtime.h>
#include <cuda_bf16.h>
#include <cstdint>

#define NENT   100000
#define NEDGE  500000
#define NSEED  10000
#define DIM    128
#define NTILE  782                  // ceil(NENT/128)
#define NROWPAD (NTILE * 128)       // 100096
#define NBLK_SCAN 98                // ceil(NENT/1024)

// dense tiling: persistent 512-thread blocks, W resident, single-pass tf32
#define LDT 132                     // padded stride (words)
#define SMEM_D (2 * 128 * LDT * 4)  // A + B tf32 planes = 135168 bytes
#define DENSE_GRID 148

// ---------------- device scratch (per-graph where concurrent) ----------------
__device__ int   g_cntbuf[2][NENT];
__device__ int   g_rowptr[2][NENT + 1];
__device__ int   g_cursor[2][NENT];
__device__ int   g_col[2][2 * NEDGE];
__device__ float g_rinv[2][NENT];
__device__ float g_hid[(size_t)NENT * DIM];
__device__ float g_agg[(size_t)NROWPAD * DIM];      // tail rows stay zero forever
__device__ uint32_t g_Wt[2][DIM * DIM];             // [layer], transposed [n][k], tf32 bits
__device__ int   g_lb[2][NBLK_SCAN];                // lookback state (zero at entry)

// ---------------- helpers ----------------
__device__ __forceinline__ uint32_t f2tf32(float x) {
    uint32_t u;
    asm("cvt.rna.tf32.f32 %0, %1;" : "=r"(u) : "f"(x));
    return u;
}
__device__ __forceinline__ void mma_tf32(float* c, const uint32_t* a, const uint32_t* b) {
    asm volatile(
        "mma.sync.aligned.m16n8k8.row.col.f32.tf32.tf32.f32 "
        "{%0,%1,%2,%3}, {%4,%5,%6,%7}, {%8,%9}, {%0,%1,%2,%3};"
        : "+f"(c[0]), "+f"(c[1]), "+f"(c[2]), "+f"(c[3])
        : "r"(a[0]), "r"(a[1]), "r"(a[2]), "r"(a[3]), "r"(b[0]), "r"(b[1]));
}

// ---------------- W prep: transposed [n][k] tf32 ----------------
__global__ void k_wprep(const float* __restrict__ W1, const float* __restrict__ W2) {
    const float* W = blockIdx.x ? W2 : W1;
    int which = blockIdx.x;
    int n = threadIdx.x;
    for (int k = 0; k < DIM; k++)
        g_Wt[which][n * DIM + k] = f2tf32(W[k * DIM + n]);
}

// ---------------- graph build ----------------
__global__ void k_count(const int* __restrict__ edges, int wg) {
    int i = blockIdx.x * blockDim.x + threadIdx.x;
    if (i < NEDGE) {
        int2 e = ((const int2*)edges)[i];
        atomicAdd(&g_cntbuf[wg][e.x], 1);
        atomicAdd(&g_cntbuf[wg][e.y], 1);
    }
}

// single-kernel scan: block-local scan + decoupled lookback (flag 1=AGG, 2=PREFIX)
__global__ void k_scanf(int wg) {
    __shared__ int wsum[32];
    __shared__ int s_pref;
    const int* cnt = g_cntbuf[wg];
    int tid = threadIdx.x, lane = tid & 31, w = tid >> 5;
    int b = blockIdx.x;
    int i = b * 1024 + tid;
    int v = (i < NENT) ? cnt[i] : 0;
    int x = v;
    #pragma unroll
    for (int off = 1; off < 32; off <<= 1) {
        int t = __shfl_up_sync(0xffffffffu, x, off);
        if (lane >= off) x += t;
    }
    if (lane == 31) wsum[w] = x;
    __syncthreads();
    if (w == 0) {
        int y = wsum[lane];
        #pragma unroll
        for (int off = 1; off < 32; off <<= 1) {
            int t = __shfl_up_sync(0xffffffffu, y, off);
            if (lane >= off) y += t;
        }
        wsum[lane] = y;
    }
    __syncthreads();
    int total = wsum[31];
    int excl = ((w > 0) ? wsum[w - 1] : 0) + x - v;

    if (tid == 0) {
        if (b == 0) {
            atomicExch(&g_lb[wg][0], (2 << 24) | total);
            s_pref = 0;
        } else {
            atomicExch(&g_lb[wg][b], (1 << 24) | total);
            int run = 0, j = b - 1;
            while (true) {
                int p = atomicAdd(&g_lb[wg][j], 0);
                int fl = p >> 24;
                if (fl == 0) continue;
                run += p & 0xffffff;
                if (fl == 2) break;
                j--;
            }
            atomicExch(&g_lb[wg][b], (2 << 24) | (run + total));
            s_pref = run;
        }
    }
    __syncthreads();
    int base = s_pref + excl;
    if (i < NENT) {
        g_rowptr[wg][i] = base;
        g_cursor[wg][i] = base;
        g_rinv[wg][i] = rsqrtf((float)(v + 1));
    }
    if (i == 0) g_rowptr[wg][NENT] = 2 * NEDGE;
}

__global__ void k_fill(const int* __restrict__ edges, int wg) {
    int i = blockIdx.x * blockDim.x + threadIdx.x;
    if (i < NEDGE) {
        int2 e = ((const int2*)edges)[i];
        int p = atomicAdd(&g_cursor[wg][e.y], 1); g_col[wg][p] = e.x;
        int q = atomicAdd(&g_cursor[wg][e.x], 1); g_col[wg][q] = e.y;
    }
}

// ---------------- aggregation (1 node per warp, unroll 4; streaming output) ----------------
__global__ void k_aggc(const float* __restrict__ x, int wg) {
    int gw   = (blockIdx.x * blockDim.x + threadIdx.x) >> 5;
    int lane = threadIdx.x & 31;
    if (gw >= NENT) return;
    int v = gw;
    int beg = g_rowptr[wg][v], end = g_rowptr[wg][v + 1];
    const int* col = g_col[wg];
    const float* rinv = g_rinv[wg];
    float rv = rinv[v];
    const float4* x4 = (const float4*)x;
    float4 a = x4[(size_t)v * 32 + lane];
    float selfn = rv * rv;
    float4 acc;
    acc.x = a.x * selfn; acc.y = a.y * selfn; acc.z = a.z * selfn; acc.w = a.w * selfn;
    int e = beg;
    for (; e + 4 <= end; e += 4) {
        int u0 = col[e], u1 = col[e + 1], u2 = col[e + 2], u3 = col[e + 3];
        float n0 = rv * rinv[u0], n1 = rv * rinv[u1];
        float n2 = rv * rinv[u2], n3 = rv * rinv[u3];
        float4 a0 = x4[(size_t)u0 * 32 + lane];
        float4 a1 = x4[(size_t)u1 * 32 + lane];
        float4 a2 = x4[(size_t)u2 * 32 + lane];
        float4 a3 = x4[(size_t)u3 * 32 + lane];
        acc.x = fmaf(a0.x, n0, acc.x); acc.y = fmaf(a0.y, n0, acc.y);
        acc.z = fmaf(a0.z, n0, acc.z); acc.w = fmaf(a0.w, n0, acc.w);
        acc.x = fmaf(a1.x, n1, acc.x); acc.y = fmaf(a1.y, n1, acc.y);
        acc.z = fmaf(a1.z, n1, acc.z); acc.w = fmaf(a1.w, n1, acc.w);
        acc.x = fmaf(a2.x, n2, acc.x); acc.y = fmaf(a2.y, n2, acc.y);
        acc.z = fmaf(a2.z, n2, acc.z); acc.w = fmaf(a2.w, n2, acc.w);
        acc.x = fmaf(a3.x, n3, acc.x); acc.y = fmaf(a3.y, n3, acc.y);
        acc.z = fmaf(a3.z, n3, acc.z); acc.w = fmaf(a3.w, n3, acc.w);
    }
    for (; e < end; e++) {
        int u = col[e];
        float nm = rv * rinv[u];
        float4 xu = x4[(size_t)u * 32 + lane];
        acc.x = fmaf(xu.x, nm, acc.x);
        acc.y = fmaf(xu.y, nm, acc.y);
        acc.z = fmaf(xu.z, nm, acc.z);
        acc.w = fmaf(xu.w, nm, acc.w);
    }
    __stcs(((float4*)g_agg) + (size_t)v * 32 + lane, acc);   // evict-first: protect x in L2
}

// ---------------- dense: persistent, W resident; out = relu(g_agg @ W + xin) ----------------
__global__ void __launch_bounds__(512, 1) k_dense_mma(const float* __restrict__ xin, int which,
                                                      float* __restrict__ out) {
    extern __shared__ uint32_t smem[];
    uint32_t* sA = smem;                 // [128][LDT] tf32 bits
    uint32_t* sB = sA + 128 * LDT;       // [128][LDT] tf32 bits, [n][k]

    int tid = threadIdx.x;
    int wid = tid >> 5, lane = tid & 31;
    int warp_m = wid & 3, warp_n = wid >> 2;      // 4x4 warps, 32x32 tiles
    int g = lane >> 2, tig = lane & 3;

    // stage B once (64 KB, resident across tiles)
    {
        const uint4* src = (const uint4*)g_Wt[which];
        #pragma unroll
        for (int t = 0; t < 8; t++) {
            int idx4 = tid + t * 512;
            int row = idx4 >> 5, col4 = (idx4 & 31) << 2;
            *(uint4*)(sB + row * LDT + col4) = src[idx4];
        }
    }

    for (int bm = blockIdx.x; bm < NTILE; bm += DENSE_GRID) {
        __syncthreads();   // prev tile's mainloop done; sB ready on first pass
        // stage A with on-the-fly tf32 conversion (read-once: evict-first)
        {
            const float4* src = (const float4*)(g_agg + (size_t)bm * 128 * DIM);
            #pragma unroll
            for (int t = 0; t < 8; t++) {
                int idx4 = tid + t * 512;
                int row = idx4 >> 5, col4 = (idx4 & 31) << 2;
                float4 f = __ldcs(src + idx4);
                uint32_t* d = sA + row * LDT + col4;
                d[0] = f2tf32(f.x); d[1] = f2tf32(f.y);
                d[2] = f2tf32(f.z); d[3] = f2tf32(f.w);
            }
        }
        __syncthreads();

        float acc[2][4][4];
        #pragma unroll
        for (int mi = 0; mi < 2; mi++)
            #pragma unroll
            for (int ni = 0; ni < 4; ni++)
                #pragma unroll
                for (int q = 0; q < 4; q++) acc[mi][ni][q] = 0.f;

        const uint32_t* pA = sA + (warp_m * 32 + g) * LDT + tig;
        const uint32_t* pB = sB + (warp_n * 32 + g) * LDT + tig;

        #pragma unroll
        for (int kk = 0; kk < 16; kk++) {
            int k0 = kk * 8;
            uint32_t a[2][4];
            #pragma unroll
            for (int mi = 0; mi < 2; mi++) {
                a[mi][0] = pA[(mi * 16) * LDT + k0];
                a[mi][1] = pA[(mi * 16 + 8) * LDT + k0];
                a[mi][2] = pA[(mi * 16) * LDT + k0 + 4];
                a[mi][3] = pA[(mi * 16 + 8) * LDT + k0 + 4];
            }
            #pragma unroll
            for (int ni = 0; ni < 4; ni++) {
                uint32_t b[2];
                b[0] = pB[(ni * 8 - (g & 24)) * LDT + k0];
                b[1] = pB[(ni * 8 - (g & 24)) * LDT + k0 + 4];
                #pragma unroll
                for (int mi = 0; mi < 2; mi++)
                    mma_tf32(acc[mi][ni], a[mi], b);
            }
        }

        // epilogue: residual + relu
        #pragma unroll
        for (int mi = 0; mi < 2; mi++) {
            int r0 = bm * 128 + warp_m * 32 + mi * 16 + g;
            int r1 = r0 + 8;
            #pragma unroll
            for (int ni = 0; ni < 4; ni++) {
                int c = warp_n * 32 + ni * 8 + tig * 2;
                if (r0 < NENT) {
                    float2 xv = __ldcs((const float2*)(xin + (size_t)r0 * DIM + c));
                    float2 o;
                    o.x = fmaxf(acc[mi][ni][0] + xv.x, 0.f);
                    o.y = fmaxf(acc[mi][ni][1] + xv.y, 0.f);
                    if (which) __stcs((float2*)(out + (size_t)r0 * DIM + c), o);
                    else       *(float2*)(out + (size_t)r0 * DIM + c) = o;
                }
                if (r1 < NENT) {
                    float2 xv = __ldcs((const float2*)(xin + (size_t)r1 * DIM + c));
                    float2 o;
                    o.x = fmaxf(acc[mi][ni][2] + xv.x, 0.f);
                    o.y = fmaxf(acc[mi][ni][3] + xv.y, 0.f);
                    if (which) __stcs((float2*)(out + (size_t)r1 * DIM + c), o);
                    else       *(float2*)(out + (size_t)r1 * DIM + c) = o;
                }
            }
        }
    }
}

// ---------------- seed gather ----------------
__global__ void k_seed(const int* __restrict__ seeds, const float* __restrict__ ent,
                       float* __restrict__ out) {
    int gw   = (blockIdx.x * blockDim.x + threadIdx.x) >> 5;
    int lane = threadIdx.x & 31;
    if (gw >= NSEED) return;
    int s = seeds[gw];
    ((float4*)out)[(size_t)gw * 32 + lane] = ((const float4*)ent)[(size_t)s * 32 + lane];
}

// ---------------- cleanup: restore zeroed state for next replay ----------------
__global__ void k_cleanup() {
    int i = blockIdx.x * 1024 + threadIdx.x;
    if (i < NENT) { g_cntbuf[0][i] = 0; g_cntbuf[1][i] = 0; }
    if (i < NBLK_SCAN) { g_lb[0][i] = 0; g_lb[1][i] = 0; }
}

// ---------------- launch ----------------
extern "C" void kernel_launch(void* const* d_in, const int* in_sizes, int n_in,
                              void* d_out, int out_size) {
    const int*   sr_seeds = (const int*)d_in[0];
    const int*   tg_seeds = (const int*)d_in[1];
    const float* emb_sr   = (const float*)d_in[4];
    const float* emb_tg   = (const float*)d_in[5];
    const int*   edges_sr = (const int*)d_in[6];
    const int*   edges_tg = (const int*)d_in[7];
    const float* W1       = (const float*)d_in[8];
    const float* W2       = (const float*)d_in[9];

    float* out         = (float*)d_out;
    float* sr_seed_out = out;
    float* tg_seed_out = out + (size_t)NSEED * DIM;
    float* sr_ent_out  = out + (size_t)2 * NSEED * DIM;
    float* tg_ent_out  = out + (size_t)2 * NSEED * DIM + (size_t)NENT * DIM;

    cudaFuncSetAttribute(k_dense_mma, cudaFuncAttributeMaxDynamicSharedMemorySize, SMEM_D);

    float* hid = nullptr;
    cudaGetSymbolAddress((void**)&hid, g_hid);

    int tE = (NEDGE + 255) / 256;

    cudaStream_t s1;
    cudaStreamCreateWithFlags(&s1, cudaStreamNonBlocking);
    cudaEvent_t evFork, evJoin;
    cudaEventCreateWithFlags(&evFork, cudaEventDisableTiming);
    cudaEventCreateWithFlags(&evJoin, cudaEventDisableTiming);

    // ---- graph 0 build on s0 ----
    k_count<<<tE, 256>>>(edges_sr, 0);           // 0
    k_scanf<<<NBLK_SCAN, 1024>>>(0);             // 1
    k_fill <<<tE, 256>>>(edges_sr, 0);           // 2
    cudaEventRecord(evFork, 0);                  // fork point (after fill0)
    k_aggc<<<12500, 256>>>(emb_sr, 0);           // 3  <- profiled slot (stcs variant)

    // ---- graph 1 build on s1, executes concurrently with graph-0 compute ----
    cudaStreamWaitEvent(s1, evFork, 0);
    k_count<<<tE, 256, 0, s1>>>(edges_tg, 1);    // 4
    k_scanf<<<NBLK_SCAN, 1024, 0, s1>>>(1);      // 5
    k_fill <<<tE, 256, 0, s1>>>(edges_tg, 1);    // 6
    cudaEventRecord(evJoin, s1);

    // ---- graph 0 compute (serial on s0) ----
    k_wprep<<<2, 128>>>(W1, W2);                 // 7
    k_dense_mma<<<DENSE_GRID, 512, SMEM_D>>>(emb_sr, 0, hid);
    k_aggc<<<12500, 256>>>(hid, 0);
    k_dense_mma<<<DENSE_GRID, 512, SMEM_D>>>(hid, 1, sr_ent_out);
    k_seed<<<(NSEED * 32 + 255) / 256, 256>>>(sr_seeds, sr_ent_out, sr_seed_out);

    // ---- join, then graph 1 compute (serial on s0) ----
    cudaStreamWaitEvent(0, evJoin, 0);
    k_aggc<<<12500, 256>>>(emb_tg, 1);
    k_dense_mma<<<DENSE_GRID, 512, SMEM_D>>>(emb_tg, 0, hid);
    k_aggc<<<12500, 256>>>(hid, 1);
    k_dense_mma<<<DENSE_GRID, 512, SMEM_D>>>(hid, 1, tg_ent_out);
    k_seed<<<(NSEED * 32 + 255) / 256, 256>>>(tg_seeds, tg_ent_out, tg_seed_out);

    k_cleanup<<<NBLK_SCAN, 1024>>>();

    cudaEventDestroy(evFork);
    cudaEventDestroy(evJoin);
    cudaStreamDestroy(s1);
}